// round 15
// baseline (speedup 1.0000x reference)
#include <cuda_runtime.h>
#include <cuda_bf16.h>
#include <cuda_fp16.h>
#include <stdint.h>

#define N_NODES 50000
#define F_IN    256
#define F_HID   128
#define NEG_SLOPE 0.01f
#define MAXE    800000
#define SCAN_B  1024
#define NSCAN   ((N_NODES + SCAN_B - 1) / SCAN_B)   // 49

// ---------------- scratch ------------------------------------------------------
__device__ __align__(16) int    g_hist[N_NODES];
__device__ __align__(16) int    g_off[N_NODES + 1];
__device__ __align__(16) int    g_cursor[N_NODES];
__device__ __align__(16) int2   g_epack[MAXE];     // (src, bitcast(deginv[src]))
__device__ __align__(16) float  g_deginv[N_NODES];
__device__ volatile unsigned long long g_states[NSCAN];
__device__ int    g_ticket;
__device__ __align__(16) __half g_xh[(size_t)N_NODES * 256];    // fp16 x
__device__ __align__(16) __half g_w1h[256 * 128];               // fp16 W1, [k][n]
__device__ __align__(16) __half g_w2h[128 * 128];               // fp16 [Wmu|Wlv], [k][n]
__device__ __align__(16) __half g_hs1h[(size_t)N_NODES * 128];  // layer-1 rows (UNscaled)
__device__ __align__(16) __half g_hs2h[(size_t)N_NODES * 128];  // layer-2 rows (pre-scaled)
__device__ __align__(16) __half g_a2h[(size_t)N_NODES * 128];   // agg2 output (fp16)

// ---------------- PTX helpers ---------------------------------------------------
__device__ __forceinline__ uint32_t smem_u32(const void* p) {
    uint32_t a;
    asm("{ .reg .u64 t; cvta.to.shared.u64 t, %1; cvt.u32.u64 %0, t; }" : "=r"(a) : "l"(p));
    return a;
}
#define CP16(dst, src) \
    asm volatile("cp.async.cg.shared.global [%0], [%1], 16;" :: "r"(dst), "l"(src))
#define CP_COMMIT() asm volatile("cp.async.commit_group;")
#define CP_WAIT1()  asm volatile("cp.async.wait_group 1;")
#define CP_WAIT0()  asm volatile("cp.async.wait_group 0;")

__device__ __forceinline__ void ldsm_x4(uint32_t& r0, uint32_t& r1, uint32_t& r2,
                                        uint32_t& r3, uint32_t addr) {
    asm volatile("ldmatrix.sync.aligned.m8n8.x4.shared.b16 {%0,%1,%2,%3}, [%4];"
                 : "=r"(r0), "=r"(r1), "=r"(r2), "=r"(r3) : "r"(addr));
}
__device__ __forceinline__ void ldsm_x4t(uint32_t& r0, uint32_t& r1, uint32_t& r2,
                                         uint32_t& r3, uint32_t addr) {
    asm volatile("ldmatrix.sync.aligned.m8n8.x4.trans.shared.b16 {%0,%1,%2,%3}, [%4];"
                 : "=r"(r0), "=r"(r1), "=r"(r2), "=r"(r3) : "r"(addr));
}
__device__ __forceinline__ void mma16816h(float* c, const uint32_t* a, uint32_t b0, uint32_t b1) {
    asm volatile("mma.sync.aligned.m16n8k16.row.col.f32.f16.f16.f32 "
                 "{%0,%1,%2,%3}, {%4,%5,%6,%7}, {%8,%9}, {%0,%1,%2,%3};"
                 : "+f"(c[0]), "+f"(c[1]), "+f"(c[2]), "+f"(c[3])
                 : "r"(a[0]), "r"(a[1]), "r"(a[2]), "r"(a[3]), "r"(b0), "r"(b1));
}
__device__ __forceinline__ uint32_t pack_h(__half a, __half b) {
    return (uint32_t)__half_as_ushort(a) | ((uint32_t)__half_as_ushort(b) << 16);
}
__device__ __forceinline__ float4 ld_row4h(const __half* base, int lane) {
    uint2 u = __ldg(reinterpret_cast<const uint2*>(base) + lane);
    __half2 h0 = *reinterpret_cast<__half2*>(&u.x);
    __half2 h1 = *reinterpret_cast<__half2*>(&u.y);
    float2 f0 = __half22float2(h0), f1 = __half22float2(h1);
    return make_float4(f0.x, f0.y, f1.x, f1.y);
}

// ---------------- stream-B prep: convert x, W1, W2 to fp16 ---------------------------
#define XF4 (N_NODES * 64)          // float4s in x
#define W1F4 (256 * 128 / 4)        // 8192
#define W2F4 (128 * 128 / 4)        // 4096

__device__ __forceinline__ uint2 cvt4(float4 v) {
    uint2 o;
    *reinterpret_cast<__half2*>(&o.x) = __floats2half2_rn(v.x, v.y);
    *reinterpret_cast<__half2*>(&o.y) = __floats2half2_rn(v.z, v.w);
    return o;
}
__global__ void convert_kernel(const float* __restrict__ x, const float* __restrict__ W1,
                               const float* __restrict__ Wmu, const float* __restrict__ Wlv) {
    int i = blockIdx.x * blockDim.x + threadIdx.x;
    if (i < XF4) {
        reinterpret_cast<uint2*>(g_xh)[i] = cvt4(reinterpret_cast<const float4*>(x)[i]);
    } else if (i < XF4 + W1F4) {
        int j = i - XF4;
        reinterpret_cast<uint2*>(g_w1h)[j] = cvt4(reinterpret_cast<const float4*>(W1)[j]);
    } else if (i < XF4 + W1F4 + W2F4) {
        int j = i - XF4 - W1F4;        // float4 over [k][n] of concatenated W2
        int e0 = j * 4;                // element index
        int k = e0 >> 7, n = e0 & 127; // 4 consecutive n, same half (64-aligned)
        const float* wsrc = (n < 64) ? (Wmu + k * 64 + n) : (Wlv + k * 64 + (n - 64));
        reinterpret_cast<uint2*>(g_w2h)[j] = cvt4(*reinterpret_cast<const float4*>(wsrc));
    }
}

// hist: 4 edges/thread (int4). Requires g_hist zeroed on entry (module-load
// zero-init; place_kernel re-zeroes every call).
__global__ void hist_kernel(const int* __restrict__ dst, int E) {
    int i = (blockIdx.x * blockDim.x + threadIdx.x) * 4;
    if (i + 3 < E) {
        int4 d = *reinterpret_cast<const int4*>(dst + i);
        atomicAdd(&g_hist[d.x], 1);
        atomicAdd(&g_hist[d.y], 1);
        atomicAdd(&g_hist[d.z], 1);
        atomicAdd(&g_hist[d.w], 1);
    } else {
        for (; i < E; i++) atomicAdd(&g_hist[dst[i]], 1);
    }
}

// ---------------- single-pass decoupled-lookback scan (1024 thr, 49 blocks) ----------
__device__ __forceinline__ int block_exscan(int v, int tid, int* total) {
    __shared__ int wsum[32];
    int lane = tid & 31, w = tid >> 5;
    int x = v;
#pragma unroll
    for (int o = 1; o < 32; o <<= 1) {
        int t = __shfl_up_sync(0xFFFFFFFFu, x, o);
        if (lane >= o) x += t;
    }
    if (lane == 31) wsum[w] = x;
    __syncthreads();
    if (w == 0) {
        int s = wsum[lane];
#pragma unroll
        for (int o = 1; o < 32; o <<= 1) {
            int t = __shfl_up_sync(0xFFFFFFFFu, s, o);
            if (lane >= o) s += t;
        }
        wsum[lane] = s;
    }
    __syncthreads();
    int woff = (w == 0) ? 0 : wsum[w - 1];
    *total = wsum[31];
    return woff + x - v;
}

__global__ void scan_kernel(int n, int E) {
    __shared__ int sbid;
    __shared__ int srun;
    if (threadIdx.x == 0) sbid = atomicAdd(&g_ticket, 1);
    __syncthreads();
    const int bid = sbid;
    const int i = bid * SCAN_B + threadIdx.x;
    const int lane = threadIdx.x & 31;
    int v = (i < n) ? g_hist[i] : 0;
    if (i < n) g_deginv[i] = rsqrtf(1.0f + (float)v);
    int tot;
    int ex = block_exscan(v, threadIdx.x, &tot);

    if (threadIdx.x < 32) {
        if (bid == 0) {
            if (lane == 0) {
                g_states[0] = ((unsigned long long)tot << 2) | 2ull;
                srun = 0;
            }
        } else {
            if (lane == 0)
                g_states[bid] = ((unsigned long long)tot << 2) | 1ull;
            int run = 0;
            int hi = bid - 1;
            while (true) {
                int j = hi - lane;
                unsigned long long s = 0;
                if (j >= 0) {
                    do { s = g_states[j]; } while ((s & 3ull) == 0ull);
                }
                unsigned msk = __ballot_sync(0xFFFFFFFFu, (j >= 0) && ((s & 3ull) == 2ull));
                int contrib;
                if (msk) {
                    int leader = __ffs(msk) - 1;
                    contrib = (lane <= leader && j >= 0) ? (int)(s >> 2) : 0;
                } else {
                    contrib = (j >= 0) ? (int)(s >> 2) : 0;
                }
#pragma unroll
                for (int o = 16; o > 0; o >>= 1)
                    contrib += __shfl_down_sync(0xFFFFFFFFu, contrib, o);
                run += __shfl_sync(0xFFFFFFFFu, contrib, 0);
                if (msk) break;
                hi -= 32;
            }
            if (lane == 0) {
                g_states[bid] = ((unsigned long long)(run + tot) << 2) | 2ull;
                srun = run;
            }
        }
    }
    __syncthreads();
    if (i < n) {
        int o = ex + srun;
        g_off[i] = o;
        g_cursor[i] = o;
    }
    if (i == 0) g_off[n] = E;
}

// place: 2 edges/thread; packed (src, deginv[src]) sorted by dst; recycles CSR state.
__global__ void place_kernel(const int* __restrict__ src, const int* __restrict__ dst, int E) {
    int t = blockIdx.x * blockDim.x + threadIdx.x;
    if (t < N_NODES) g_hist[t] = 0;
    if (t < NSCAN) g_states[t] = 0ull;
    if (t == 0) g_ticket = 0;
    int e = t * 2;
    if (e + 1 < E) {
        int2 s2 = *reinterpret_cast<const int2*>(src + e);
        int2 d2 = *reinterpret_cast<const int2*>(dst + e);
        float da = __ldg(&g_deginv[s2.x]);
        float db = __ldg(&g_deginv[s2.y]);
        int pa = atomicAdd(&g_cursor[d2.x], 1);
        int pb = atomicAdd(&g_cursor[d2.y], 1);
        g_epack[pa] = make_int2(s2.x, __float_as_int(da));
        g_epack[pb] = make_int2(s2.y, __float_as_int(db));
    } else {
        for (; e < E; e++) {
            int s = __ldg(&src[e]);
            float d = __ldg(&g_deginv[s]);
            int pos = atomicAdd(&g_cursor[dst[e]], 1);
            g_epack[pos] = make_int2(s, __float_as_int(d));
        }
    }
}

// ---------------- shared GEMM tile constants ----------------------------------------
#define A_PITCH 40
#define B_PITCH 136
#define A_BUF   (128 * A_PITCH * 2)
#define B_BUF   (32 * B_PITCH * 2)

struct SmemG {
    __half As[2][128 * A_PITCH];
    __half Bs[2][32 * B_PITCH];
};

// ---------------- GEMM1: hs1 = xh @ W1h (fp16 cp.async pipeline, K=256) --------------
__global__ void __launch_bounds__(256)
mma_gemm1_kernel(__half* __restrict__ hs1, int M) {
    __shared__ SmemG sm;
    const int tid = threadIdx.x;
    const int lane = tid & 31, wid = tid >> 5;
    const int warp_m = wid & 3, warp_n = wid >> 2;
    const int block_row = blockIdx.x * 128;

    const int ar = tid >> 2, aseg = tid & 3;
    const int bk = tid >> 4, bseg = tid & 15;
    const int g0 = min(block_row + ar, M - 1);
    const int g1 = min(block_row + ar + 64, M - 1);
    const __half* ap0 = g_xh + (size_t)g0 * 256 + aseg * 8;
    const __half* ap1 = g_xh + (size_t)g1 * 256 + aseg * 8;
    const uint32_t asm0 = smem_u32(&sm.As[0][ar * A_PITCH + aseg * 8]);
    const uint32_t asm1 = smem_u32(&sm.As[0][(ar + 64) * A_PITCH + aseg * 8]);
    const uint32_t bsm0 = smem_u32(&sm.Bs[0][bk * B_PITCH + bseg * 8]);
    const uint32_t bsm1 = smem_u32(&sm.Bs[0][(bk + 16) * B_PITCH + bseg * 8]);
    const uint32_t a_ld0 = smem_u32(&sm.As[0][0]);
    const uint32_t b_ld0 = smem_u32(&sm.Bs[0][0]);

    float c[2][8][4];
#pragma unroll
    for (int i = 0; i < 2; i++)
#pragma unroll
        for (int j = 0; j < 8; j++)
#pragma unroll
            for (int q = 0; q < 4; q++) c[i][j][q] = 0.0f;

    const int NT = 256 / 32;  // 8
#define ISSUE1(it, buf) do { \
        int _kk = (it) * 32; \
        CP16(asm0 + (buf) * A_BUF, ap0 + _kk); \
        CP16(asm1 + (buf) * A_BUF, ap1 + _kk); \
        CP16(bsm0 + (buf) * B_BUF, g_w1h + (size_t)(_kk + bk) * 128 + bseg * 8); \
        CP16(bsm1 + (buf) * B_BUF, g_w1h + (size_t)(_kk + bk + 16) * 128 + bseg * 8); \
        CP_COMMIT(); \
    } while (0)

    ISSUE1(0, 0);
#pragma unroll 1
    for (int it = 0; it < NT; it++) {
        const int p = it & 1;
        if (it + 1 < NT) { ISSUE1(it + 1, p ^ 1); CP_WAIT1(); }
        else            { CP_WAIT0(); }
        __syncthreads();
        const uint32_t abase = a_ld0 + p * A_BUF;
        const uint32_t bbase = b_ld0 + p * B_BUF;
#pragma unroll
        for (int ks = 0; ks < 2; ks++) {
            uint32_t a[2][4], b[4][4];
#pragma unroll
            for (int mt = 0; mt < 2; mt++) {
                int row = warp_m * 32 + mt * 16 + (lane & 15);
                int col = ks * 16 + (lane >> 4) * 8;
                ldsm_x4(a[mt][0], a[mt][1], a[mt][2], a[mt][3],
                        abase + (row * A_PITCH + col) * 2);
            }
#pragma unroll
            for (int np = 0; np < 4; np++) {
                int row = ks * 16 + (lane & 7) + ((lane >> 3) & 1) * 8;
                int col = warp_n * 64 + np * 16 + (lane >> 4) * 8;
                ldsm_x4t(b[np][0], b[np][1], b[np][2], b[np][3],
                         bbase + (row * B_PITCH + col) * 2);
            }
#pragma unroll
            for (int mt = 0; mt < 2; mt++)
#pragma unroll
                for (int nt = 0; nt < 8; nt++)
                    mma16816h(c[mt][nt], a[mt],
                              b[nt >> 1][(nt & 1) * 2], b[nt >> 1][(nt & 1) * 2 + 1]);
        }
        __syncthreads();
    }
#undef ISSUE1

#pragma unroll
    for (int mt = 0; mt < 2; mt++) {
        int row0 = block_row + warp_m * 32 + mt * 16 + (lane >> 2);
        int row1 = row0 + 8;
#pragma unroll
        for (int nt = 0; nt < 8; nt++) {
            int col = warp_n * 64 + nt * 8 + (lane & 3) * 2;
            if (row0 < M)
                *reinterpret_cast<__half2*>(hs1 + (size_t)row0 * 128 + col) =
                    __floats2half2_rn(c[mt][nt][0], c[mt][nt][1]);
            if (row1 < M)
                *reinterpret_cast<__half2*>(hs1 + (size_t)row1 * 128 + col) =
                    __floats2half2_rn(c[mt][nt][2], c[mt][nt][3]);
        }
    }
}

// --------- agg1: warp/node; acc = di*hs1[n] + sum(d_s*hs1[s]) via packed edges;
//           h = leaky(di*acc + b1); hs2 = h*di (pre-scaled) -------------------------
__global__ void __launch_bounds__(256)
agg1_kernel(const __half* __restrict__ hs1, const float* __restrict__ b1,
            __half* __restrict__ hs2, int N) {
    int node = (blockIdx.x * blockDim.x + threadIdx.x) >> 5;
    int lane = threadIdx.x & 31;
    if (node >= N) return;
    int beg = g_off[node], end = g_off[node + 1];
    float di = __ldg(&g_deginv[node]);
    float4 sv = ld_row4h(hs1 + (size_t)node * 128, lane);
    float4 acc = make_float4(sv.x * di, sv.y * di, sv.z * di, sv.w * di);
    int j = beg;
    for (; j + 7 < end; j += 8) {
        int2 e[8];
        float4 v[8];
#pragma unroll
        for (int k = 0; k < 8; k++) e[k] = __ldg(&g_epack[j + k]);
#pragma unroll
        for (int k = 0; k < 8; k++) v[k] = ld_row4h(hs1 + (size_t)e[k].x * 128, lane);
#pragma unroll
        for (int k = 0; k < 8; k++) {
            float d = __int_as_float(e[k].y);
            acc.x += v[k].x * d; acc.y += v[k].y * d;
            acc.z += v[k].z * d; acc.w += v[k].w * d;
        }
    }
    for (; j < end; j++) {
        int2 e = __ldg(&g_epack[j]);
        float d = __int_as_float(e.y);
        float4 v = ld_row4h(hs1 + (size_t)e.x * 128, lane);
        acc.x += v.x * d; acc.y += v.y * d; acc.z += v.z * d; acc.w += v.w * d;
    }
    float4 b = __ldg(reinterpret_cast<const float4*>(b1) + lane);
    float4 v;
    v.x = acc.x * di + b.x; v.y = acc.y * di + b.y;
    v.z = acc.z * di + b.z; v.w = acc.w * di + b.w;
    v.x = (v.x > 0.f) ? v.x : v.x * NEG_SLOPE;
    v.y = (v.y > 0.f) ? v.y : v.y * NEG_SLOPE;
    v.z = (v.z > 0.f) ? v.z : v.z * NEG_SLOPE;
    v.w = (v.w > 0.f) ? v.w : v.w * NEG_SLOPE;
    uint2 o;
    *reinterpret_cast<__half2*>(&o.x) = __floats2half2_rn(v.x * di, v.y * di);
    *reinterpret_cast<__half2*>(&o.y) = __floats2half2_rn(v.z * di, v.w * di);
    reinterpret_cast<uint2*>(hs2 + (size_t)node * 128)[lane] = o;
}

// --------- agg2: warp/node (hs2 pre-scaled); scale; write fp16 rows ------------------
__global__ void __launch_bounds__(256)
agg2_kernel(const __half* __restrict__ hs2, __half* __restrict__ a2, int N) {
    int node = (blockIdx.x * blockDim.x + threadIdx.x) >> 5;
    int lane = threadIdx.x & 31;
    if (node >= N) return;
    int beg = g_off[node], end = g_off[node + 1];
    float4 acc = ld_row4h(hs2 + (size_t)node * 128, lane);
    int j = beg;
    for (; j + 7 < end; j += 8) {
        int s[8];
        float4 v[8];
#pragma unroll
        for (int k = 0; k < 8; k++) s[k] = __ldg(&g_epack[j + k]).x;
#pragma unroll
        for (int k = 0; k < 8; k++) v[k] = ld_row4h(hs2 + (size_t)s[k] * 128, lane);
#pragma unroll
        for (int k = 0; k < 8; k++) {
            acc.x += v[k].x; acc.y += v[k].y; acc.z += v[k].z; acc.w += v[k].w;
        }
    }
    for (; j < end; j++) {
        int s = __ldg(&g_epack[j]).x;
        float4 v = ld_row4h(hs2 + (size_t)s * 128, lane);
        acc.x += v.x; acc.y += v.y; acc.z += v.z; acc.w += v.w;
    }
    float di = __ldg(&g_deginv[node]);
    uint2 o;
    *reinterpret_cast<__half2*>(&o.x) = __floats2half2_rn(acc.x * di, acc.y * di);
    *reinterpret_cast<__half2*>(&o.y) = __floats2half2_rn(acc.z * di, acc.w * di);
    reinterpret_cast<uint2*>(a2 + (size_t)node * 128)[lane] = o;
}

// ---------------- GEMM2: out = a2 @ W2 (fp16 single-pass) + bias --------------------
__global__ void __launch_bounds__(256)
mma_gemm2_kernel(const __half* __restrict__ A,
                 const float* __restrict__ bmu, const float* __restrict__ blv,
                 float* __restrict__ out, int M) {
    __shared__ SmemG sm;
    const int tid = threadIdx.x;
    const int lane = tid & 31, wid = tid >> 5;
    const int warp_m = wid & 3, warp_n = wid >> 2;
    const int block_row = blockIdx.x * 128;

    const int ar = tid >> 2, aseg = tid & 3;
    const int bk = tid >> 4, bseg = tid & 15;
    const int g0 = min(block_row + ar, M - 1);
    const int g1 = min(block_row + ar + 64, M - 1);
    const __half* ap0 = A + (size_t)g0 * 128 + aseg * 8;
    const __half* ap1 = A + (size_t)g1 * 128 + aseg * 8;
    const uint32_t asm0 = smem_u32(&sm.As[0][ar * A_PITCH + aseg * 8]);
    const uint32_t asm1 = smem_u32(&sm.As[0][(ar + 64) * A_PITCH + aseg * 8]);
    const uint32_t bsm0 = smem_u32(&sm.Bs[0][bk * B_PITCH + bseg * 8]);
    const uint32_t bsm1 = smem_u32(&sm.Bs[0][(bk + 16) * B_PITCH + bseg * 8]);
    const uint32_t a_ld0 = smem_u32(&sm.As[0][0]);
    const uint32_t b_ld0 = smem_u32(&sm.Bs[0][0]);

    float c[2][8][4];
#pragma unroll
    for (int i = 0; i < 2; i++)
#pragma unroll
        for (int j = 0; j < 8; j++)
#pragma unroll
            for (int q = 0; q < 4; q++) c[i][j][q] = 0.0f;

    const int NT = 128 / 32;
#define ISSUE2(it, buf) do { \
        int _kk = (it) * 32; \
        CP16(asm0 + (buf) * A_BUF, ap0 + _kk); \
        CP16(asm1 + (buf) * A_BUF, ap1 + _kk); \
        CP16(bsm0 + (buf) * B_BUF, g_w2h + (size_t)(_kk + bk) * 128 + bseg * 8); \
        CP16(bsm1 + (buf) * B_BUF, g_w2h + (size_t)(_kk + bk + 16) * 128 + bseg * 8); \
        CP_COMMIT(); \
    } while (0)

    ISSUE2(0, 0);
#pragma unroll 1
    for (int it = 0; it < NT; it++) {
        const int p = it & 1;
        if (it + 1 < NT) { ISSUE2(it + 1, p ^ 1); CP_WAIT1(); }
        else            { CP_WAIT0(); }
        __syncthreads();
        const uint32_t abase = a_ld0 + p * A_BUF;
        const uint32_t bbase = b_ld0 + p * B_BUF;
#pragma unroll
        for (int ks = 0; ks < 2; ks++) {
            uint32_t a[2][4], b[4][4];
#pragma unroll
            for (int mt = 0; mt < 2; mt++) {
                int row = warp_m * 32 + mt * 16 + (lane & 15);
                int col = ks * 16 + (lane >> 4) * 8;
                ldsm_x4(a[mt][0], a[mt][1], a[mt][2], a[mt][3],
                        abase + (row * A_PITCH + col) * 2);
            }
#pragma unroll
            for (int np = 0; np < 4; np++) {
                int row = ks * 16 + (lane & 7) + ((lane >> 3) & 1) * 8;
                int col = warp_n * 64 + np * 16 + (lane >> 4) * 8;
                ldsm_x4t(b[np][0], b[np][1], b[np][2], b[np][3],
                         bbase + (row * B_PITCH + col) * 2);
            }
#pragma unroll
            for (int mt = 0; mt < 2; mt++)
#pragma unroll
                for (int nt = 0; nt < 8; nt++)
                    mma16816h(c[mt][nt], a[mt],
                              b[nt >> 1][(nt & 1) * 2], b[nt >> 1][(nt & 1) * 2 + 1]);
        }
        __syncthreads();
    }
#undef ISSUE2

    const float* bias = warp_n ? blv : bmu;
    float* base = out + (warp_n ? (size_t)M * 64 : 0);
#pragma unroll
    for (int mt = 0; mt < 2; mt++) {
        int row0 = block_row + warp_m * 32 + mt * 16 + (lane >> 2);
        int row1 = row0 + 8;
#pragma unroll
        for (int nt = 0; nt < 8; nt++) {
            int col = nt * 8 + (lane & 3) * 2;
            float b0 = __ldg(&bias[col]), b1 = __ldg(&bias[col + 1]);
            if (row0 < M)
                *reinterpret_cast<float2*>(base + (size_t)row0 * 64 + col) =
                    make_float2(c[mt][nt][0] + b0, c[mt][nt][1] + b1);
            if (row1 < M)
                *reinterpret_cast<float2*>(base + (size_t)row1 * 64 + col) =
                    make_float2(c[mt][nt][2] + b0, c[mt][nt][3] + b1);
        }
    }
}

// ---------------- launch ---------------------------------------------------------------
extern "C" void kernel_launch(void* const* d_in, const int* in_sizes, int n_in,
                              void* d_out, int out_size) {
    const float* x   = (const float*)d_in[0];
    const int*   ei  = (const int*)d_in[1];   // int32 (JAX x64 disabled)
    const float* W1  = (const float*)d_in[2];
    const float* b1  = (const float*)d_in[3];
    const float* Wmu = (const float*)d_in[4];
    const float* bmu = (const float*)d_in[5];
    const float* Wlv = (const float*)d_in[6];
    const float* blv = (const float*)d_in[7];
    float* out = (float*)d_out;

    const int N = in_sizes[0] / F_IN;  // 50000
    const int E = in_sizes[1] / 2;     // 800000
    const int* src = ei;
    const int* dst = ei + E;

    __half *hs1, *hs2, *a2;
    cudaGetSymbolAddress((void**)&hs1, g_hs1h);
    cudaGetSymbolAddress((void**)&hs2, g_hs2h);
    cudaGetSymbolAddress((void**)&a2,  g_a2h);

    static cudaStream_t sB = nullptr;
    static cudaEvent_t evFork = nullptr, evJoin = nullptr;
    if (sB == nullptr) {
        cudaStreamCreateWithFlags(&sB, cudaStreamNonBlocking);
        cudaEventCreateWithFlags(&evFork, cudaEventDisableTiming);
        cudaEventCreateWithFlags(&evJoin, cudaEventDisableTiming);
    }

    // fork: stream B = convert + GEMM1 (independent of graph structure)
    cudaEventRecord(evFork, 0);
    cudaStreamWaitEvent(sB, evFork, 0);
    int convBlocks = (XF4 + W1F4 + W2F4 + 255) / 256;
    convert_kernel<<<convBlocks, 256, 0, sB>>>(x, W1, Wmu, Wlv);
    mma_gemm1_kernel<<<(N + 127) / 128, 256, 0, sB>>>(hs1, N);
    cudaEventRecord(evJoin, sB);

    // stream A (default): CSR build
    hist_kernel<<<(E / 4 + 255) / 256, 256>>>(dst, E);
    scan_kernel<<<NSCAN, SCAN_B>>>(N, E);
    place_kernel<<<(E / 2 + 255) / 256, 256>>>(src, dst, E);

    // join, then the dependent chain (W2 was converted before GEMM1 on stream B)
    cudaStreamWaitEvent(0, evJoin, 0);
    agg1_kernel<<<(N * 32 + 255) / 256, 256>>>(hs1, b1, hs2, N);
    agg2_kernel<<<(N * 32 + 255) / 256, 256>>>(hs2, a2, N);
    mma_gemm2_kernel<<<(N + 127) / 128, 256>>>(a2, bmu, blv, out, N);
}

// round 16
// speedup vs baseline: 1.0192x; 1.0192x over previous
#include <cuda_runtime.h>
#include <cuda_bf16.h>
#include <cuda_fp16.h>
#include <stdint.h>

#define N_NODES 50000
#define F_IN    256
#define F_HID   128
#define NEG_SLOPE 0.01f
#define MAXE    800000
#define SCAN_B  1024
#define NSCAN   ((N_NODES + SCAN_B - 1) / SCAN_B)   // 49

// ---------------- scratch ------------------------------------------------------
__device__ __align__(16) int    g_hist[N_NODES];
__device__ __align__(16) int    g_off[N_NODES + 1];
__device__ __align__(16) int    g_cursor[N_NODES];
__device__ __align__(16) int2   g_epack[MAXE];     // (src, bitcast(deginv[src]))
__device__ __align__(16) float  g_deginv[N_NODES];
__device__ volatile unsigned long long g_states[NSCAN];
__device__ int    g_ticket;
__device__ __align__(16) __half g_w1h[256 * 128];               // fp16 W1, [k][n]
__device__ __align__(16) __half g_w2h[128 * 128];               // fp16 [Wmu|Wlv], [k][n]
__device__ __align__(16) __half g_hs1h[(size_t)N_NODES * 128];  // layer-1 rows (UNscaled)
__device__ __align__(16) __half g_hs2h[(size_t)N_NODES * 128];  // layer-2 rows (pre-scaled)
__device__ __align__(16) __half g_a2h[(size_t)N_NODES * 128];   // agg2 output (fp16)

// ---------------- PTX helpers ---------------------------------------------------
__device__ __forceinline__ uint32_t smem_u32(const void* p) {
    uint32_t a;
    asm("{ .reg .u64 t; cvta.to.shared.u64 t, %1; cvt.u32.u64 %0, t; }" : "=r"(a) : "l"(p));
    return a;
}
#define CP16(dst, src) \
    asm volatile("cp.async.cg.shared.global [%0], [%1], 16;" :: "r"(dst), "l"(src))
#define CP_COMMIT() asm volatile("cp.async.commit_group;")
#define CP_WAIT1()  asm volatile("cp.async.wait_group 1;")
#define CP_WAIT0()  asm volatile("cp.async.wait_group 0;")

__device__ __forceinline__ void ldsm_x4(uint32_t& r0, uint32_t& r1, uint32_t& r2,
                                        uint32_t& r3, uint32_t addr) {
    asm volatile("ldmatrix.sync.aligned.m8n8.x4.shared.b16 {%0,%1,%2,%3}, [%4];"
                 : "=r"(r0), "=r"(r1), "=r"(r2), "=r"(r3) : "r"(addr));
}
__device__ __forceinline__ void ldsm_x4t(uint32_t& r0, uint32_t& r1, uint32_t& r2,
                                         uint32_t& r3, uint32_t addr) {
    asm volatile("ldmatrix.sync.aligned.m8n8.x4.trans.shared.b16 {%0,%1,%2,%3}, [%4];"
                 : "=r"(r0), "=r"(r1), "=r"(r2), "=r"(r3) : "r"(addr));
}
__device__ __forceinline__ void mma16816h(float* c, const uint32_t* a, uint32_t b0, uint32_t b1) {
    asm volatile("mma.sync.aligned.m16n8k16.row.col.f32.f16.f16.f32 "
                 "{%0,%1,%2,%3}, {%4,%5,%6,%7}, {%8,%9}, {%0,%1,%2,%3};"
                 : "+f"(c[0]), "+f"(c[1]), "+f"(c[2]), "+f"(c[3])
                 : "r"(a[0]), "r"(a[1]), "r"(a[2]), "r"(a[3]), "r"(b0), "r"(b1));
}
__device__ __forceinline__ uint32_t pack_h(__half a, __half b) {
    return (uint32_t)__half_as_ushort(a) | ((uint32_t)__half_as_ushort(b) << 16);
}
__device__ __forceinline__ float4 ld_row4h(const __half* base, int lane) {
    uint2 u = __ldg(reinterpret_cast<const uint2*>(base) + lane);
    __half2 h0 = *reinterpret_cast<__half2*>(&u.x);
    __half2 h1 = *reinterpret_cast<__half2*>(&u.y);
    float2 f0 = __half22float2(h0), f1 = __half22float2(h1);
    return make_float4(f0.x, f0.y, f1.x, f1.y);
}

// ---------------- weight conversions (split) -----------------------------------------
__global__ void prep_w1_kernel(const float* __restrict__ W1) {
    int i = blockIdx.x * blockDim.x + threadIdx.x;
    if (i < 256 * 128) g_w1h[i] = __float2half(W1[i]);
}
__global__ void prep_w2_kernel(const float* __restrict__ Wmu, const float* __restrict__ Wlv) {
    int i = blockIdx.x * blockDim.x + threadIdx.x;
    if (i < 128 * 128) {
        int k = i >> 7, n = i & 127;
        float w = (n < 64) ? Wmu[k * 64 + n] : Wlv[k * 64 + (n - 64)];
        g_w2h[i] = __float2half(w);
    }
}

// hist: 4 edges/thread (int4). Requires g_hist zeroed on entry (module-load
// zero-init; place_kernel re-zeroes every call).
__global__ void hist_kernel(const int* __restrict__ dst, int E) {
    int i = (blockIdx.x * blockDim.x + threadIdx.x) * 4;
    if (i + 3 < E) {
        int4 d = *reinterpret_cast<const int4*>(dst + i);
        atomicAdd(&g_hist[d.x], 1);
        atomicAdd(&g_hist[d.y], 1);
        atomicAdd(&g_hist[d.z], 1);
        atomicAdd(&g_hist[d.w], 1);
    } else {
        for (; i < E; i++) atomicAdd(&g_hist[dst[i]], 1);
    }
}

// ---------------- single-pass decoupled-lookback scan (1024 thr, 49 blocks) ----------
__device__ __forceinline__ int block_exscan(int v, int tid, int* total) {
    __shared__ int wsum[32];
    int lane = tid & 31, w = tid >> 5;
    int x = v;
#pragma unroll
    for (int o = 1; o < 32; o <<= 1) {
        int t = __shfl_up_sync(0xFFFFFFFFu, x, o);
        if (lane >= o) x += t;
    }
    if (lane == 31) wsum[w] = x;
    __syncthreads();
    if (w == 0) {
        int s = wsum[lane];
#pragma unroll
        for (int o = 1; o < 32; o <<= 1) {
            int t = __shfl_up_sync(0xFFFFFFFFu, s, o);
            if (lane >= o) s += t;
        }
        wsum[lane] = s;
    }
    __syncthreads();
    int woff = (w == 0) ? 0 : wsum[w - 1];
    *total = wsum[31];
    return woff + x - v;
}

__global__ void scan_kernel(int n, int E) {
    __shared__ int sbid;
    __shared__ int srun;
    if (threadIdx.x == 0) sbid = atomicAdd(&g_ticket, 1);
    __syncthreads();
    const int bid = sbid;
    const int i = bid * SCAN_B + threadIdx.x;
    const int lane = threadIdx.x & 31;
    int v = (i < n) ? g_hist[i] : 0;
    if (i < n) g_deginv[i] = rsqrtf(1.0f + (float)v);
    int tot;
    int ex = block_exscan(v, threadIdx.x, &tot);

    if (threadIdx.x < 32) {
        if (bid == 0) {
            if (lane == 0) {
                g_states[0] = ((unsigned long long)tot << 2) | 2ull;
                srun = 0;
            }
        } else {
            if (lane == 0)
                g_states[bid] = ((unsigned long long)tot << 2) | 1ull;
            int run = 0;
            int hi = bid - 1;
            while (true) {
                int j = hi - lane;
                unsigned long long s = 0;
                if (j >= 0) {
                    do { s = g_states[j]; } while ((s & 3ull) == 0ull);
                }
                unsigned msk = __ballot_sync(0xFFFFFFFFu, (j >= 0) && ((s & 3ull) == 2ull));
                int contrib;
                if (msk) {
                    int leader = __ffs(msk) - 1;
                    contrib = (lane <= leader && j >= 0) ? (int)(s >> 2) : 0;
                } else {
                    contrib = (j >= 0) ? (int)(s >> 2) : 0;
                }
#pragma unroll
                for (int o = 16; o > 0; o >>= 1)
                    contrib += __shfl_down_sync(0xFFFFFFFFu, contrib, o);
                run += __shfl_sync(0xFFFFFFFFu, contrib, 0);
                if (msk) break;
                hi -= 32;
            }
            if (lane == 0) {
                g_states[bid] = ((unsigned long long)(run + tot) << 2) | 2ull;
                srun = run;
            }
        }
    }
    __syncthreads();
    if (i < n) {
        int o = ex + srun;
        g_off[i] = o;
        g_cursor[i] = o;
    }
    if (i == 0) g_off[n] = E;
}

// place: 2 edges/thread; packed (src, deginv[src]) sorted by dst; recycles CSR state.
__global__ void place_kernel(const int* __restrict__ src, const int* __restrict__ dst, int E) {
    int t = blockIdx.x * blockDim.x + threadIdx.x;
    if (t < N_NODES) g_hist[t] = 0;
    if (t < NSCAN) g_states[t] = 0ull;
    if (t == 0) g_ticket = 0;
    int e = t * 2;
    if (e + 1 < E) {
        int2 s2 = *reinterpret_cast<const int2*>(src + e);
        int2 d2 = *reinterpret_cast<const int2*>(dst + e);
        float da = __ldg(&g_deginv[s2.x]);
        float db = __ldg(&g_deginv[s2.y]);
        int pa = atomicAdd(&g_cursor[d2.x], 1);
        int pb = atomicAdd(&g_cursor[d2.y], 1);
        g_epack[pa] = make_int2(s2.x, __float_as_int(da));
        g_epack[pb] = make_int2(s2.y, __float_as_int(db));
    } else {
        for (; e < E; e++) {
            int s = __ldg(&src[e]);
            float d = __ldg(&g_deginv[s]);
            int pos = atomicAdd(&g_cursor[dst[e]], 1);
            g_epack[pos] = make_int2(s, __float_as_int(d));
        }
    }
}

// ---------------- GEMM1: hs1 = x@W1, fused fp32->fp16 convert (R14 proven) ----------
#define A_PITCH 40
#define B_PITCH 136
#define A_BUF   (128 * A_PITCH * 2)
#define B_BUF   (32 * B_PITCH * 2)
#define SM1_A   0
#define SM1_B   (SM1_A + 2 * A_BUF)
#define SM1_BYTES (SM1_B + 2 * B_BUF)   // 37888

__global__ void __launch_bounds__(256)
mma_gemm1_kernel(const float* __restrict__ x, __half* __restrict__ hs1, int M) {
    extern __shared__ __align__(16) uint8_t smem[];
    const uint32_t sbase = smem_u32(smem);
    const int tid = threadIdx.x;
    const int lane = tid & 31, wid = tid >> 5;
    const int warp_m = wid & 3, warp_n = wid >> 2;
    const int block_row = blockIdx.x * 128;

    const int arow = tid >> 1, acol = (tid & 1) * 16;
    const int grow = min(block_row + arow, M - 1);
    const float* ap = x + (size_t)grow * 256 + acol;
    const uint32_t a_sts = sbase + SM1_A + (arow * A_PITCH + acol) * 2;

    const int bk = tid >> 4, bseg = tid & 15;
    const uint32_t b_sts_0 = sbase + SM1_B + (bk * B_PITCH + bseg * 8) * 2;
    const uint32_t b_sts_1 = sbase + SM1_B + ((bk + 16) * B_PITCH + bseg * 8) * 2;

    float c[2][8][4];
#pragma unroll
    for (int i = 0; i < 2; i++)
#pragma unroll
        for (int j = 0; j < 8; j++)
#pragma unroll
            for (int q = 0; q < 4; q++) c[i][j][q] = 0.0f;

    float4 areg[4];
#define LDG_A(k0) do { \
        areg[0] = *reinterpret_cast<const float4*>(ap + (k0)); \
        areg[1] = *reinterpret_cast<const float4*>(ap + (k0) + 4); \
        areg[2] = *reinterpret_cast<const float4*>(ap + (k0) + 8); \
        areg[3] = *reinterpret_cast<const float4*>(ap + (k0) + 12); \
    } while (0)
#define STS_A(buf) do { \
        uint4 uh; uint32_t* ph = &uh.x; \
        _Pragma("unroll") \
        for (int q2 = 0; q2 < 2; q2++) { \
            _Pragma("unroll") \
            for (int q = 0; q < 2; q++) { \
                float4 f = areg[q2 * 2 + q]; \
                ph[q * 2 + 0] = pack_h(__float2half(f.x), __float2half(f.y)); \
                ph[q * 2 + 1] = pack_h(__float2half(f.z), __float2half(f.w)); \
            } \
            *reinterpret_cast<uint4*>( \
                (uint8_t*)smem + (a_sts - sbase) + (buf) * A_BUF + q2 * 16) = uh; \
        } \
    } while (0)
#define CP_B(k0, buf) do { \
        CP16(b_sts_0 + (buf) * B_BUF, g_w1h + (size_t)((k0) + bk) * 128 + bseg * 8); \
        CP16(b_sts_1 + (buf) * B_BUF, g_w1h + (size_t)((k0) + bk + 16) * 128 + bseg * 8); \
        CP_COMMIT(); \
    } while (0)

    LDG_A(0);
    CP_B(0, 0);
    STS_A(0);

    const int NT = 256 / 32;
#pragma unroll 1
    for (int t = 0; t < NT; t++) {
        const int p = t & 1;
        if (t + 1 < NT) {
            LDG_A((t + 1) * 32);
            CP_B((t + 1) * 32, p ^ 1);
            CP_WAIT1();
        } else {
            CP_WAIT0();
        }
        __syncthreads();
        if (t + 1 < NT) STS_A(p ^ 1);

        const uint32_t a_b = sbase + SM1_A + p * A_BUF;
        const uint32_t b_b = sbase + SM1_B + p * B_BUF;
#pragma unroll
        for (int ks = 0; ks < 2; ks++) {
            uint32_t a[2][4], b[4][4];
#pragma unroll
            for (int mt = 0; mt < 2; mt++) {
                int row = warp_m * 32 + mt * 16 + (lane & 15);
                int col = ks * 16 + (lane >> 4) * 8;
                ldsm_x4(a[mt][0], a[mt][1], a[mt][2], a[mt][3],
                        a_b + (row * A_PITCH + col) * 2);
            }
#pragma unroll
            for (int np = 0; np < 4; np++) {
                int row = ks * 16 + (lane & 7) + ((lane >> 3) & 1) * 8;
                int col = warp_n * 64 + np * 16 + (lane >> 4) * 8;
                ldsm_x4t(b[np][0], b[np][1], b[np][2], b[np][3],
                         b_b + (row * B_PITCH + col) * 2);
            }
#pragma unroll
            for (int mt = 0; mt < 2; mt++)
#pragma unroll
                for (int nt = 0; nt < 8; nt++)
                    mma16816h(c[mt][nt], a[mt],
                              b[nt >> 1][(nt & 1) * 2], b[nt >> 1][(nt & 1) * 2 + 1]);
        }
        __syncthreads();
    }
#undef LDG_A
#undef STS_A
#undef CP_B

#pragma unroll
    for (int mt = 0; mt < 2; mt++) {
        int row0 = block_row + warp_m * 32 + mt * 16 + (lane >> 2);
        int row1 = row0 + 8;
#pragma unroll
        for (int nt = 0; nt < 8; nt++) {
            int col = warp_n * 64 + nt * 8 + (lane & 3) * 2;
            if (row0 < M)
                *reinterpret_cast<__half2*>(hs1 + (size_t)row0 * 128 + col) =
                    __floats2half2_rn(c[mt][nt][0], c[mt][nt][1]);
            if (row1 < M)
                *reinterpret_cast<__half2*>(hs1 + (size_t)row1 * 128 + col) =
                    __floats2half2_rn(c[mt][nt][2], c[mt][nt][3]);
        }
    }
}

// --------- agg1: warp/node; acc = di*hs1[n] + sum(d_s*hs1[s]) via packed edges;
//           h = leaky(di*acc + b1); hs2 = h*di (pre-scaled) -------------------------
__global__ void __launch_bounds__(256)
agg1_kernel(const __half* __restrict__ hs1, const float* __restrict__ b1,
            __half* __restrict__ hs2, int N) {
    int node = (blockIdx.x * blockDim.x + threadIdx.x) >> 5;
    int lane = threadIdx.x & 31;
    if (node >= N) return;
    int beg = g_off[node], end = g_off[node + 1];
    float di = __ldg(&g_deginv[node]);
    float4 sv = ld_row4h(hs1 + (size_t)node * 128, lane);
    float4 acc = make_float4(sv.x * di, sv.y * di, sv.z * di, sv.w * di);
    int j = beg;
    for (; j + 7 < end; j += 8) {
        int2 e[8];
        float4 v[8];
#pragma unroll
        for (int k = 0; k < 8; k++) e[k] = __ldg(&g_epack[j + k]);
#pragma unroll
        for (int k = 0; k < 8; k++) v[k] = ld_row4h(hs1 + (size_t)e[k].x * 128, lane);
#pragma unroll
        for (int k = 0; k < 8; k++) {
            float d = __int_as_float(e[k].y);
            acc.x += v[k].x * d; acc.y += v[k].y * d;
            acc.z += v[k].z * d; acc.w += v[k].w * d;
        }
    }
    for (; j < end; j++) {
        int2 e = __ldg(&g_epack[j]);
        float d = __int_as_float(e.y);
        float4 v = ld_row4h(hs1 + (size_t)e.x * 128, lane);
        acc.x += v.x * d; acc.y += v.y * d; acc.z += v.z * d; acc.w += v.w * d;
    }
    float4 b = __ldg(reinterpret_cast<const float4*>(b1) + lane);
    float4 v;
    v.x = acc.x * di + b.x; v.y = acc.y * di + b.y;
    v.z = acc.z * di + b.z; v.w = acc.w * di + b.w;
    v.x = (v.x > 0.f) ? v.x : v.x * NEG_SLOPE;
    v.y = (v.y > 0.f) ? v.y : v.y * NEG_SLOPE;
    v.z = (v.z > 0.f) ? v.z : v.z * NEG_SLOPE;
    v.w = (v.w > 0.f) ? v.w : v.w * NEG_SLOPE;
    uint2 o;
    *reinterpret_cast<__half2*>(&o.x) = __floats2half2_rn(v.x * di, v.y * di);
    *reinterpret_cast<__half2*>(&o.y) = __floats2half2_rn(v.z * di, v.w * di);
    reinterpret_cast<uint2*>(hs2 + (size_t)node * 128)[lane] = o;
}

// --------- agg2 (node range [base, base+count)): gather + scale -> fp16 rows ---------
__global__ void __launch_bounds__(256)
agg2_kernel(const __half* __restrict__ hs2, __half* __restrict__ a2,
            int base, int count) {
    int idx = (blockIdx.x * blockDim.x + threadIdx.x) >> 5;
    int lane = threadIdx.x & 31;
    if (idx >= count) return;
    int node = base + idx;
    int beg = g_off[node], end = g_off[node + 1];
    float4 acc = ld_row4h(hs2 + (size_t)node * 128, lane);
    int j = beg;
    for (; j + 7 < end; j += 8) {
        int s[8];
        float4 v[8];
#pragma unroll
        for (int k = 0; k < 8; k++) s[k] = __ldg(&g_epack[j + k]).x;
#pragma unroll
        for (int k = 0; k < 8; k++) v[k] = ld_row4h(hs2 + (size_t)s[k] * 128, lane);
#pragma unroll
        for (int k = 0; k < 8; k++) {
            acc.x += v[k].x; acc.y += v[k].y; acc.z += v[k].z; acc.w += v[k].w;
        }
    }
    for (; j < end; j++) {
        int s = __ldg(&g_epack[j]).x;
        float4 v = ld_row4h(hs2 + (size_t)s * 128, lane);
        acc.x += v.x; acc.y += v.y; acc.z += v.z; acc.w += v.w;
    }
    float di = __ldg(&g_deginv[node]);
    uint2 o;
    *reinterpret_cast<__half2*>(&o.x) = __floats2half2_rn(acc.x * di, acc.y * di);
    *reinterpret_cast<__half2*>(&o.y) = __floats2half2_rn(acc.z * di, acc.w * di);
    reinterpret_cast<uint2*>(a2 + (size_t)node * 128)[lane] = o;
}

// ---------------- GEMM2 (row range): out rows [base, base+count) ---------------------
struct Smem2 {
    __half As[2][128 * A_PITCH];
    __half Bs[2][32 * B_PITCH];
};
__global__ void __launch_bounds__(256)
mma_gemm2_kernel(const __half* __restrict__ A,
                 const float* __restrict__ bmu, const float* __restrict__ blv,
                 float* __restrict__ out, int M, int base, int count) {
    __shared__ Smem2 sm;
    const int tid = threadIdx.x;
    const int lane = tid & 31, wid = tid >> 5;
    const int warp_m = wid & 3, warp_n = wid >> 2;
    const int block_row = base + blockIdx.x * 128;
    const int row_lim = base + count;

    const int ar = tid >> 2, aseg = tid & 3;
    const int bk = tid >> 4, bseg = tid & 15;
    const int g0 = min(block_row + ar, row_lim - 1);
    const int g1 = min(block_row + ar + 64, row_lim - 1);
    const __half* ap0 = A + (size_t)g0 * 128 + aseg * 8;
    const __half* ap1 = A + (size_t)g1 * 128 + aseg * 8;
    const uint32_t asm0 = smem_u32(&sm.As[0][ar * A_PITCH + aseg * 8]);
    const uint32_t asm1 = smem_u32(&sm.As[0][(ar + 64) * A_PITCH + aseg * 8]);
    const uint32_t bsm0 = smem_u32(&sm.Bs[0][bk * B_PITCH + bseg * 8]);
    const uint32_t bsm1 = smem_u32(&sm.Bs[0][(bk + 16) * B_PITCH + bseg * 8]);
    const uint32_t a_ld0 = smem_u32(&sm.As[0][0]);
    const uint32_t b_ld0 = smem_u32(&sm.Bs[0][0]);

    float c[2][8][4];
#pragma unroll
    for (int i = 0; i < 2; i++)
#pragma unroll
        for (int j = 0; j < 8; j++)
#pragma unroll
            for (int q = 0; q < 4; q++) c[i][j][q] = 0.0f;

    const int NT = 128 / 32;
#define ISSUE2(it, buf) do { \
        int _kk = (it) * 32; \
        CP16(asm0 + (buf) * A_BUF, ap0 + _kk); \
        CP16(asm1 + (buf) * A_BUF, ap1 + _kk); \
        CP16(bsm0 + (buf) * B_BUF, g_w2h + (size_t)(_kk + bk) * 128 + bseg * 8); \
        CP16(bsm1 + (buf) * B_BUF, g_w2h + (size_t)(_kk + bk + 16) * 128 + bseg * 8); \
        CP_COMMIT(); \
    } while (0)

    ISSUE2(0, 0);
#pragma unroll 1
    for (int it = 0; it < NT; it++) {
        const int p = it & 1;
        if (it + 1 < NT) { ISSUE2(it + 1, p ^ 1); CP_WAIT1(); }
        else            { CP_WAIT0(); }
        __syncthreads();
        const uint32_t abase = a_ld0 + p * A_BUF;
        const uint32_t bbase = b_ld0 + p * B_BUF;
#pragma unroll
        for (int ks = 0; ks < 2; ks++) {
            uint32_t a[2][4], b[4][4];
#pragma unroll
            for (int mt = 0; mt < 2; mt++) {
                int row = warp_m * 32 + mt * 16 + (lane & 15);
                int col = ks * 16 + (lane >> 4) * 8;
                ldsm_x4(a[mt][0], a[mt][1], a[mt][2], a[mt][3],
                        abase + (row * A_PITCH + col) * 2);
            }
#pragma unroll
            for (int np = 0; np < 4; np++) {
                int row = ks * 16 + (lane & 7) + ((lane >> 3) & 1) * 8;
                int col = warp_n * 64 + np * 16 + (lane >> 4) * 8;
                ldsm_x4t(b[np][0], b[np][1], b[np][2], b[np][3],
                         bbase + (row * B_PITCH + col) * 2);
            }
#pragma unroll
            for (int mt = 0; mt < 2; mt++)
#pragma unroll
                for (int nt = 0; nt < 8; nt++)
                    mma16816h(c[mt][nt], a[mt],
                              b[nt >> 1][(nt & 1) * 2], b[nt >> 1][(nt & 1) * 2 + 1]);
        }
        __syncthreads();
    }
#undef ISSUE2

    const float* bias = warp_n ? blv : bmu;
    float* obase = out + (warp_n ? (size_t)M * 64 : 0);
#pragma unroll
    for (int mt = 0; mt < 2; mt++) {
        int row0 = block_row + warp_m * 32 + mt * 16 + (lane >> 2);
        int row1 = row0 + 8;
#pragma unroll
        for (int nt = 0; nt < 8; nt++) {
            int col = nt * 8 + (lane & 3) * 2;
            float b0 = __ldg(&bias[col]), b1 = __ldg(&bias[col + 1]);
            if (row0 < row_lim)
                *reinterpret_cast<float2*>(obase + (size_t)row0 * 64 + col) =
                    make_float2(c[mt][nt][0] + b0, c[mt][nt][1] + b1);
            if (row1 < row_lim)
                *reinterpret_cast<float2*>(obase + (size_t)row1 * 64 + col) =
                    make_float2(c[mt][nt][2] + b0, c[mt][nt][3] + b1);
        }
    }
}

// ---------------- launch ---------------------------------------------------------------
extern "C" void kernel_launch(void* const* d_in, const int* in_sizes, int n_in,
                              void* d_out, int out_size) {
    const float* x   = (const float*)d_in[0];
    const int*   ei  = (const int*)d_in[1];   // int32 (JAX x64 disabled)
    const float* W1  = (const float*)d_in[2];
    const float* b1  = (const float*)d_in[3];
    const float* Wmu = (const float*)d_in[4];
    const float* bmu = (const float*)d_in[5];
    const float* Wlv = (const float*)d_in[6];
    const float* blv = (const float*)d_in[7];
    float* out = (float*)d_out;

    const int N = in_sizes[0] / F_IN;  // 50000
    const int E = in_sizes[1] / 2;     // 800000
    const int* src = ei;
    const int* dst = ei + E;

    __half *hs1, *hs2, *a2;
    cudaGetSymbolAddress((void**)&hs1, g_hs1h);
    cudaGetSymbolAddress((void**)&hs2, g_hs2h);
    cudaGetSymbolAddress((void**)&a2,  g_a2h);

    cudaFuncSetAttribute(mma_gemm1_kernel,
                         cudaFuncAttributeMaxDynamicSharedMemorySize, SM1_BYTES);

    static cudaStream_t sB = nullptr;
    static cudaEvent_t evFork = nullptr, evJoin = nullptr, evW2 = nullptr;
    static cudaEvent_t evAgg1 = nullptr, evA2b = nullptr;
    if (sB == nullptr) {
        cudaStreamCreateWithFlags(&sB, cudaStreamNonBlocking);
        cudaEventCreateWithFlags(&evFork, cudaEventDisableTiming);
        cudaEventCreateWithFlags(&evJoin, cudaEventDisableTiming);
        cudaEventCreateWithFlags(&evW2, cudaEventDisableTiming);
        cudaEventCreateWithFlags(&evAgg1, cudaEventDisableTiming);
        cudaEventCreateWithFlags(&evA2b, cudaEventDisableTiming);
    }

    // fork: stream B = W1 prep + GEMM1 (independent of graph structure)
    cudaEventRecord(evFork, 0);
    cudaStreamWaitEvent(sB, evFork, 0);
    prep_w1_kernel<<<(256 * 128 + 255) / 256, 256, 0, sB>>>(W1);
    mma_gemm1_kernel<<<(N + 127) / 128, 256, SM1_BYTES, sB>>>(x, hs1, N);
    cudaEventRecord(evJoin, sB);
    prep_w2_kernel<<<(128 * 128 + 255) / 256, 256, 0, sB>>>(Wmu, Wlv);
    cudaEventRecord(evW2, sB);

    // stream A (default): CSR build
    hist_kernel<<<(E / 4 + 255) / 256, 256>>>(dst, E);
    scan_kernel<<<NSCAN, SCAN_B>>>(N, E);
    place_kernel<<<(E / 2 + 255) / 256, 256>>>(src, dst, E);

    // join, then agg1 (full)
    cudaStreamWaitEvent(0, evJoin, 0);
    agg1_kernel<<<(N * 32 + 255) / 256, 256>>>(hs1, b1, hs2, N);
    cudaEventRecord(evAgg1, 0);

    // chunked agg2 -> GEMM2 pipeline (row-aligned dependency)
    const int h0 = ((N / 2) + 127) & ~127;   // 25088 (multiple of 128)
    const int h1 = N - h0;                   // 24912

    // chunk 0 on stream A
    agg2_kernel<<<(h0 * 32 + 255) / 256, 256>>>(hs2, a2, 0, h0);
    // chunk 1 on stream B (after agg1)
    cudaStreamWaitEvent(sB, evAgg1, 0);
    agg2_kernel<<<(h1 * 32 + 255) / 256, 256, 0, sB>>>(hs2, a2, h0, h1);
    cudaEventRecord(evA2b, sB);

    // GEMM2 chunk 0 overlaps agg2 chunk 1
    cudaStreamWaitEvent(0, evW2, 0);
    mma_gemm2_kernel<<<h0 / 128, 256>>>(a2, bmu, blv, out, N, 0, h0);
    // GEMM2 chunk 1 after agg2 chunk 1
    cudaStreamWaitEvent(0, evA2b, 0);
    mma_gemm2_kernel<<<(h1 + 127) / 128, 256>>>(a2, bmu, blv, out, N, h0, h1);
}

// round 17
// speedup vs baseline: 1.0313x; 1.0118x over previous
#include <cuda_runtime.h>
#include <cuda_bf16.h>
#include <cuda_fp16.h>
#include <stdint.h>

#define N_NODES 50000
#define F_IN    256
#define F_HID   128
#define NEG_SLOPE 0.01f
#define MAXE    800000
#define SCAN_B  1024
#define NSCAN   ((N_NODES + SCAN_B - 1) / SCAN_B)   // 49

// ---------------- scratch ------------------------------------------------------
__device__ __align__(16) int    g_hist[N_NODES];
__device__ __align__(16) int    g_off[N_NODES + 1];
__device__ __align__(16) int    g_cursor[N_NODES];
__device__ __align__(16) int2   g_epack[MAXE];     // (src, bitcast(deginv[src]))
__device__ __align__(16) float  g_deginv[N_NODES];
__device__ volatile unsigned long long g_states[NSCAN];
__device__ int    g_ticket;
__device__ __align__(16) __half g_hs1h[(size_t)N_NODES * 128];  // layer-1 rows (UNscaled)
__device__ __align__(16) __half g_hs2h[(size_t)N_NODES * 128];  // layer-2 rows (pre-scaled)
__device__ __align__(16) __half g_a2h[(size_t)N_NODES * 128];   // agg2 output (fp16)

// ---------------- PTX helpers ---------------------------------------------------
__device__ __forceinline__ uint32_t smem_u32(const void* p) {
    uint32_t a;
    asm("{ .reg .u64 t; cvta.to.shared.u64 t, %1; cvt.u32.u64 %0, t; }" : "=r"(a) : "l"(p));
    return a;
}
__device__ __forceinline__ void ldsm_x4(uint32_t& r0, uint32_t& r1, uint32_t& r2,
                                        uint32_t& r3, uint32_t addr) {
    asm volatile("ldmatrix.sync.aligned.m8n8.x4.shared.b16 {%0,%1,%2,%3}, [%4];"
                 : "=r"(r0), "=r"(r1), "=r"(r2), "=r"(r3) : "r"(addr));
}
__device__ __forceinline__ void ldsm_x4t(uint32_t& r0, uint32_t& r1, uint32_t& r2,
                                         uint32_t& r3, uint32_t addr) {
    asm volatile("ldmatrix.sync.aligned.m8n8.x4.trans.shared.b16 {%0,%1,%2,%3}, [%4];"
                 : "=r"(r0), "=r"(r1), "=r"(r2), "=r"(r3) : "r"(addr));
}
__device__ __forceinline__ void mma16816h(float* c, const uint32_t* a, uint32_t b0, uint32_t b1) {
    asm volatile("mma.sync.aligned.m16n8k16.row.col.f32.f16.f16.f32 "
                 "{%0,%1,%2,%3}, {%4,%5,%6,%7}, {%8,%9}, {%0,%1,%2,%3};"
                 : "+f"(c[0]), "+f"(c[1]), "+f"(c[2]), "+f"(c[3])
                 : "r"(a[0]), "r"(a[1]), "r"(a[2]), "r"(a[3]), "r"(b0), "r"(b1));
}
__device__ __forceinline__ uint32_t pack_h(__half a, __half b) {
    return (uint32_t)__half_as_ushort(a) | ((uint32_t)__half_as_ushort(b) << 16);
}
__device__ __forceinline__ uint4 cvt8(float4 f0, float4 f1) {
    uint4 u;
    u.x = pack_h(__float2half(f0.x), __float2half(f0.y));
    u.y = pack_h(__float2half(f0.z), __float2half(f0.w));
    u.z = pack_h(__float2half(f1.x), __float2half(f1.y));
    u.w = pack_h(__float2half(f1.z), __float2half(f1.w));
    return u;
}
__device__ __forceinline__ float4 ld_row4h(const __half* base, int lane) {
    uint2 u = __ldg(reinterpret_cast<const uint2*>(base) + lane);
    __half2 h0 = *reinterpret_cast<__half2*>(&u.x);
    __half2 h1 = *reinterpret_cast<__half2*>(&u.y);
    float2 f0 = __half22float2(h0), f1 = __half22float2(h1);
    return make_float4(f0.x, f0.y, f1.x, f1.y);
}

// hist: 4 edges/thread (int4). Requires g_hist zeroed on entry (module-load
// zero-init; place_kernel re-zeroes every call).
__global__ void hist_kernel(const int* __restrict__ dst, int E) {
    int i = (blockIdx.x * blockDim.x + threadIdx.x) * 4;
    if (i + 3 < E) {
        int4 d = *reinterpret_cast<const int4*>(dst + i);
        atomicAdd(&g_hist[d.x], 1);
        atomicAdd(&g_hist[d.y], 1);
        atomicAdd(&g_hist[d.z], 1);
        atomicAdd(&g_hist[d.w], 1);
    } else {
        for (; i < E; i++) atomicAdd(&g_hist[dst[i]], 1);
    }
}

// ---------------- single-pass decoupled-lookback scan (1024 thr, 49 blocks) ----------
__device__ __forceinline__ int block_exscan(int v, int tid, int* total) {
    __shared__ int wsum[32];
    int lane = tid & 31, w = tid >> 5;
    int x = v;
#pragma unroll
    for (int o = 1; o < 32; o <<= 1) {
        int t = __shfl_up_sync(0xFFFFFFFFu, x, o);
        if (lane >= o) x += t;
    }
    if (lane == 31) wsum[w] = x;
    __syncthreads();
    if (w == 0) {
        int s = wsum[lane];
#pragma unroll
        for (int o = 1; o < 32; o <<= 1) {
            int t = __shfl_up_sync(0xFFFFFFFFu, s, o);
            if (lane >= o) s += t;
        }
        wsum[lane] = s;
    }
    __syncthreads();
    int woff = (w == 0) ? 0 : wsum[w - 1];
    *total = wsum[31];
    return woff + x - v;
}

__global__ void scan_kernel(int n, int E) {
    __shared__ int sbid;
    __shared__ int srun;
    if (threadIdx.x == 0) sbid = atomicAdd(&g_ticket, 1);
    __syncthreads();
    const int bid = sbid;
    const int i = bid * SCAN_B + threadIdx.x;
    const int lane = threadIdx.x & 31;
    int v = (i < n) ? g_hist[i] : 0;
    if (i < n) g_deginv[i] = rsqrtf(1.0f + (float)v);
    int tot;
    int ex = block_exscan(v, threadIdx.x, &tot);

    if (threadIdx.x < 32) {
        if (bid == 0) {
            if (lane == 0) {
                g_states[0] = ((unsigned long long)tot << 2) | 2ull;
                srun = 0;
            }
        } else {
            if (lane == 0)
                g_states[bid] = ((unsigned long long)tot << 2) | 1ull;
            int run = 0;
            int hi = bid - 1;
            while (true) {
                int j = hi - lane;
                unsigned long long s = 0;
                if (j >= 0) {
                    do { s = g_states[j]; } while ((s & 3ull) == 0ull);
                }
                unsigned msk = __ballot_sync(0xFFFFFFFFu, (j >= 0) && ((s & 3ull) == 2ull));
                int contrib;
                if (msk) {
                    int leader = __ffs(msk) - 1;
                    contrib = (lane <= leader && j >= 0) ? (int)(s >> 2) : 0;
                } else {
                    contrib = (j >= 0) ? (int)(s >> 2) : 0;
                }
#pragma unroll
                for (int o = 16; o > 0; o >>= 1)
                    contrib += __shfl_down_sync(0xFFFFFFFFu, contrib, o);
                run += __shfl_sync(0xFFFFFFFFu, contrib, 0);
                if (msk) break;
                hi -= 32;
            }
            if (lane == 0) {
                g_states[bid] = ((unsigned long long)(run + tot) << 2) | 2ull;
                srun = run;
            }
        }
    }
    __syncthreads();
    if (i < n) {
        int o = ex + srun;
        g_off[i] = o;
        g_cursor[i] = o;
    }
    if (i == 0) g_off[n] = E;
}

// place: 2 edges/thread; packed (src, deginv[src]) sorted by dst; recycles CSR state.
__global__ void place_kernel(const int* __restrict__ src, const int* __restrict__ dst, int E) {
    int t = blockIdx.x * blockDim.x + threadIdx.x;
    if (t < N_NODES) g_hist[t] = 0;
    if (t < NSCAN) g_states[t] = 0ull;
    if (t == 0) g_ticket = 0;
    int e = t * 2;
    if (e + 1 < E) {
        int2 s2 = *reinterpret_cast<const int2*>(src + e);
        int2 d2 = *reinterpret_cast<const int2*>(dst + e);
        float da = __ldg(&g_deginv[s2.x]);
        float db = __ldg(&g_deginv[s2.y]);
        int pa = atomicAdd(&g_cursor[d2.x], 1);
        int pb = atomicAdd(&g_cursor[d2.y], 1);
        g_epack[pa] = make_int2(s2.x, __float_as_int(da));
        g_epack[pb] = make_int2(s2.y, __float_as_int(db));
    } else {
        for (; e < E; e++) {
            int s = __ldg(&src[e]);
            float d = __ldg(&g_deginv[s]);
            int pos = atomicAdd(&g_cursor[dst[e]], 1);
            g_epack[pos] = make_int2(s, __float_as_int(d));
        }
    }
}

// ---------------- GEMM tile constants -------------------------------------------------
#define A_PITCH 40
#define B_PITCH 136
#define A_BUF   (128 * A_PITCH * 2)
#define B_BUF   (32 * B_PITCH * 2)
#define SM_A    0
#define SM_B    (SM_A + 2 * A_BUF)
#define SM_BYTES (SM_B + 2 * B_BUF)   // 37888

// ---------------- GEMM1: hs1 = x@W1; both operands converted fp32->fp16 in-kernel ----
__global__ void __launch_bounds__(256)
mma_gemm1_kernel(const float* __restrict__ x, const float* __restrict__ W1,
                 __half* __restrict__ hs1, int M) {
    extern __shared__ __align__(16) uint8_t smem[];
    const uint32_t sbase = smem_u32(smem);
    const int tid = threadIdx.x;
    const int lane = tid & 31, wid = tid >> 5;
    const int warp_m = wid & 3, warp_n = wid >> 2;
    const int block_row = blockIdx.x * 128;

    // A: thread -> row tid>>1, 16-col half
    const int arow = tid >> 1, acol = (tid & 1) * 16;
    const int grow = min(block_row + arow, M - 1);
    const float* ap = x + (size_t)grow * 256 + acol;
    const uint32_t a_sts = sbase + SM_A + (arow * A_PITCH + acol) * 2;

    // B: thread -> rows {bk, bk+16}, 8 cols at bseg*8
    const int bk = tid >> 4, bseg = tid & 15;
    const float* bp0 = W1 + (size_t)bk * 128 + bseg * 8;
    const float* bp1 = W1 + (size_t)(bk + 16) * 128 + bseg * 8;
    const uint32_t b_sts_0 = sbase + SM_B + (bk * B_PITCH + bseg * 8) * 2;
    const uint32_t b_sts_1 = sbase + SM_B + ((bk + 16) * B_PITCH + bseg * 8) * 2;

    float c[2][8][4];
#pragma unroll
    for (int i = 0; i < 2; i++)
#pragma unroll
        for (int j = 0; j < 8; j++)
#pragma unroll
            for (int q = 0; q < 4; q++) c[i][j][q] = 0.0f;

    float4 areg[4], breg[4];
#define LDG_AB(k0) do { \
        areg[0] = *reinterpret_cast<const float4*>(ap + (k0)); \
        areg[1] = *reinterpret_cast<const float4*>(ap + (k0) + 4); \
        areg[2] = *reinterpret_cast<const float4*>(ap + (k0) + 8); \
        areg[3] = *reinterpret_cast<const float4*>(ap + (k0) + 12); \
        breg[0] = *reinterpret_cast<const float4*>(bp0 + (size_t)(k0) * 128); \
        breg[1] = *reinterpret_cast<const float4*>(bp0 + (size_t)(k0) * 128 + 4); \
        breg[2] = *reinterpret_cast<const float4*>(bp1 + (size_t)(k0) * 128); \
        breg[3] = *reinterpret_cast<const float4*>(bp1 + (size_t)(k0) * 128 + 4); \
    } while (0)
#define STS_AB(buf) do { \
        *reinterpret_cast<uint4*>((uint8_t*)smem + (a_sts - sbase) + (buf) * A_BUF) = \
            cvt8(areg[0], areg[1]); \
        *reinterpret_cast<uint4*>((uint8_t*)smem + (a_sts - sbase) + (buf) * A_BUF + 16) = \
            cvt8(areg[2], areg[3]); \
        *reinterpret_cast<uint4*>((uint8_t*)smem + (b_sts_0 - sbase) + (buf) * B_BUF) = \
            cvt8(breg[0], breg[1]); \
        *reinterpret_cast<uint4*>((uint8_t*)smem + (b_sts_1 - sbase) + (buf) * B_BUF) = \
            cvt8(breg[2], breg[3]); \
    } while (0)

    LDG_AB(0);
    STS_AB(0);
    __syncthreads();

    const int NT = 256 / 32;
#pragma unroll 1
    for (int t = 0; t < NT; t++) {
        const int p = t & 1;
        if (t + 1 < NT) LDG_AB((t + 1) * 32);

        const uint32_t a_b = sbase + SM_A + p * A_BUF;
        const uint32_t b_b = sbase + SM_B + p * B_BUF;
#pragma unroll
        for (int ks = 0; ks < 2; ks++) {
            uint32_t a[2][4], b[4][4];
#pragma unroll
            for (int mt = 0; mt < 2; mt++) {
                int row = warp_m * 32 + mt * 16 + (lane & 15);
                int col = ks * 16 + (lane >> 4) * 8;
                ldsm_x4(a[mt][0], a[mt][1], a[mt][2], a[mt][3],
                        a_b + (row * A_PITCH + col) * 2);
            }
#pragma unroll
            for (int np = 0; np < 4; np++) {
                int row = ks * 16 + (lane & 7) + ((lane >> 3) & 1) * 8;
                int col = warp_n * 64 + np * 16 + (lane >> 4) * 8;
                ldsm_x4t(b[np][0], b[np][1], b[np][2], b[np][3],
                         b_b + (row * B_PITCH + col) * 2);
            }
#pragma unroll
            for (int mt = 0; mt < 2; mt++)
#pragma unroll
                for (int nt = 0; nt < 8; nt++)
                    mma16816h(c[mt][nt], a[mt],
                              b[nt >> 1][(nt & 1) * 2], b[nt >> 1][(nt & 1) * 2 + 1]);
        }
        if (t + 1 < NT) {
            __syncthreads();          // all warps done reading buf p^1 (prev STS target)
            STS_AB(p ^ 1);
            __syncthreads();          // STS visible before compute reads it
        }
    }
#undef LDG_AB
#undef STS_AB

#pragma unroll
    for (int mt = 0; mt < 2; mt++) {
        int row0 = block_row + warp_m * 32 + mt * 16 + (lane >> 2);
        int row1 = row0 + 8;
#pragma unroll
        for (int nt = 0; nt < 8; nt++) {
            int col = warp_n * 64 + nt * 8 + (lane & 3) * 2;
            if (row0 < M)
                *reinterpret_cast<__half2*>(hs1 + (size_t)row0 * 128 + col) =
                    __floats2half2_rn(c[mt][nt][0], c[mt][nt][1]);
            if (row1 < M)
                *reinterpret_cast<__half2*>(hs1 + (size_t)row1 * 128 + col) =
                    __floats2half2_rn(c[mt][nt][2], c[mt][nt][3]);
        }
    }
}

// --------- agg1: warp/node; acc = di*hs1[n] + sum(d_s*hs1[s]) via packed edges;
//           h = leaky(di*acc + b1); hs2 = h*di (pre-scaled) -------------------------
__global__ void __launch_bounds__(256)
agg1_kernel(const __half* __restrict__ hs1, const float* __restrict__ b1,
            __half* __restrict__ hs2, int N) {
    int node = (blockIdx.x * blockDim.x + threadIdx.x) >> 5;
    int lane = threadIdx.x & 31;
    if (node >= N) return;
    int beg = g_off[node], end = g_off[node + 1];
    float di = __ldg(&g_deginv[node]);
    float4 sv = ld_row4h(hs1 + (size_t)node * 128, lane);
    float4 acc = make_float4(sv.x * di, sv.y * di, sv.z * di, sv.w * di);
    int j = beg;
    for (; j + 7 < end; j += 8) {
        int2 e[8];
        float4 v[8];
#pragma unroll
        for (int k = 0; k < 8; k++) e[k] = __ldg(&g_epack[j + k]);
#pragma unroll
        for (int k = 0; k < 8; k++) v[k] = ld_row4h(hs1 + (size_t)e[k].x * 128, lane);
#pragma unroll
        for (int k = 0; k < 8; k++) {
            float d = __int_as_float(e[k].y);
            acc.x += v[k].x * d; acc.y += v[k].y * d;
            acc.z += v[k].z * d; acc.w += v[k].w * d;
        }
    }
    for (; j < end; j++) {
        int2 e = __ldg(&g_epack[j]);
        float d = __int_as_float(e.y);
        float4 v = ld_row4h(hs1 + (size_t)e.x * 128, lane);
        acc.x += v.x * d; acc.y += v.y * d; acc.z += v.z * d; acc.w += v.w * d;
    }
    float4 b = __ldg(reinterpret_cast<const float4*>(b1) + lane);
    float4 v;
    v.x = acc.x * di + b.x; v.y = acc.y * di + b.y;
    v.z = acc.z * di + b.z; v.w = acc.w * di + b.w;
    v.x = (v.x > 0.f) ? v.x : v.x * NEG_SLOPE;
    v.y = (v.y > 0.f) ? v.y : v.y * NEG_SLOPE;
    v.z = (v.z > 0.f) ? v.z : v.z * NEG_SLOPE;
    v.w = (v.w > 0.f) ? v.w : v.w * NEG_SLOPE;
    uint2 o;
    *reinterpret_cast<__half2*>(&o.x) = __floats2half2_rn(v.x * di, v.y * di);
    *reinterpret_cast<__half2*>(&o.y) = __floats2half2_rn(v.z * di, v.w * di);
    reinterpret_cast<uint2*>(hs2 + (size_t)node * 128)[lane] = o;
}

// --------- agg2: warp/node (hs2 pre-scaled); scale; write fp16 rows ------------------
__global__ void __launch_bounds__(256)
agg2_kernel(const __half* __restrict__ hs2, __half* __restrict__ a2, int N) {
    int node = (blockIdx.x * blockDim.x + threadIdx.x) >> 5;
    int lane = threadIdx.x & 31;
    if (node >= N) return;
    int beg = g_off[node], end = g_off[node + 1];
    float4 acc = ld_row4h(hs2 + (size_t)node * 128, lane);
    int j = beg;
    for (; j + 7 < end; j += 8) {
        int s[8];
        float4 v[8];
#pragma unroll
        for (int k = 0; k < 8; k++) s[k] = __ldg(&g_epack[j + k]).x;
#pragma unroll
        for (int k = 0; k < 8; k++) v[k] = ld_row4h(hs2 + (size_t)s[k] * 128, lane);
#pragma unroll
        for (int k = 0; k < 8; k++) {
            acc.x += v[k].x; acc.y += v[k].y; acc.z += v[k].z; acc.w += v[k].w;
        }
    }
    for (; j < end; j++) {
        int s = __ldg(&g_epack[j]).x;
        float4 v = ld_row4h(hs2 + (size_t)s * 128, lane);
        acc.x += v.x; acc.y += v.y; acc.z += v.z; acc.w += v.w;
    }
    float di = __ldg(&g_deginv[node]);
    uint2 o;
    *reinterpret_cast<__half2*>(&o.x) = __floats2half2_rn(acc.x * di, acc.y * di);
    *reinterpret_cast<__half2*>(&o.y) = __floats2half2_rn(acc.z * di, acc.w * di);
    reinterpret_cast<uint2*>(a2 + (size_t)node * 128)[lane] = o;
}

// ---------------- GEMM2: out = a2 @ [Wmu|Wlv] + bias; W2 converted in-kernel ---------
__global__ void __launch_bounds__(256)
mma_gemm2_kernel(const __half* __restrict__ A,
                 const float* __restrict__ Wmu, const float* __restrict__ Wlv,
                 const float* __restrict__ bmu, const float* __restrict__ blv,
                 float* __restrict__ out, int M) {
    extern __shared__ __align__(16) uint8_t smem[];
    const uint32_t sbase = smem_u32(smem);
    const int tid = threadIdx.x;
    const int lane = tid & 31, wid = tid >> 5;
    const int warp_m = wid & 3, warp_n = wid >> 2;
    const int block_row = blockIdx.x * 128;

    // A (fp16): rows ar, ar+64; 8-halve seg
    const int ar = tid >> 2, aseg = tid & 3;
    const int g0 = min(block_row + ar, M - 1);
    const int g1 = min(block_row + ar + 64, M - 1);
    const __half* ap0 = A + (size_t)g0 * 128 + aseg * 8;
    const __half* ap1 = A + (size_t)g1 * 128 + aseg * 8;
    const uint32_t a_sts_0 = sbase + SM_A + (ar * A_PITCH + aseg * 8) * 2;
    const uint32_t a_sts_1 = sbase + SM_A + ((ar + 64) * A_PITCH + aseg * 8) * 2;

    // B (fp32 source): rows {bk, bk+16}, 8 cols at bseg*8 (all in one 64-col half)
    const int bk = tid >> 4, bseg = tid & 15;
    const int bcol = bseg * 8;
    const bool bmu0 = (bcol < 64);
    const float* bw = bmu0 ? (Wmu + bcol) : (Wlv + (bcol - 64));
    const uint32_t b_sts_0 = sbase + SM_B + (bk * B_PITCH + bcol) * 2;
    const uint32_t b_sts_1 = sbase + SM_B + ((bk + 16) * B_PITCH + bcol) * 2;

    float c[2][8][4];
#pragma unroll
    for (int i = 0; i < 2; i++)
#pragma unroll
        for (int j = 0; j < 8; j++)
#pragma unroll
            for (int q = 0; q < 4; q++) c[i][j][q] = 0.0f;

    uint4 areg[2];
    float4 breg[4];
#define LDG_AB2(k0) do { \
        areg[0] = *reinterpret_cast<const uint4*>(ap0 + (k0)); \
        areg[1] = *reinterpret_cast<const uint4*>(ap1 + (k0)); \
        breg[0] = *reinterpret_cast<const float4*>(bw + (size_t)((k0) + bk) * 64); \
        breg[1] = *reinterpret_cast<const float4*>(bw + (size_t)((k0) + bk) * 64 + 4); \
        breg[2] = *reinterpret_cast<const float4*>(bw + (size_t)((k0) + bk + 16) * 64); \
        breg[3] = *reinterpret_cast<const float4*>(bw + (size_t)((k0) + bk + 16) * 64 + 4); \
    } while (0)
#define STS_AB2(buf) do { \
        *reinterpret_cast<uint4*>((uint8_t*)smem + (a_sts_0 - sbase) + (buf) * A_BUF) = areg[0]; \
        *reinterpret_cast<uint4*>((uint8_t*)smem + (a_sts_1 - sbase) + (buf) * A_BUF) = areg[1]; \
        *reinterpret_cast<uint4*>((uint8_t*)smem + (b_sts_0 - sbase) + (buf) * B_BUF) = \
            cvt8(breg[0], breg[1]); \
        *reinterpret_cast<uint4*>((uint8_t*)smem + (b_sts_1 - sbase) + (buf) * B_BUF) = \
            cvt8(breg[2], breg[3]); \
    } while (0)

    LDG_AB2(0);
    STS_AB2(0);
    __syncthreads();

    const int NT = 128 / 32;
#pragma unroll 1
    for (int t = 0; t < NT; t++) {
        const int p = t & 1;
        if (t + 1 < NT) LDG_AB2((t + 1) * 32);

        const uint32_t a_b = sbase + SM_A + p * A_BUF;
        const uint32_t b_b = sbase + SM_B + p * B_BUF;
#pragma unroll
        for (int ks = 0; ks < 2; ks++) {
            uint32_t a[2][4], b[4][4];
#pragma unroll
            for (int mt = 0; mt < 2; mt++) {
                int row = warp_m * 32 + mt * 16 + (lane & 15);
                int col = ks * 16 + (lane >> 4) * 8;
                ldsm_x4(a[mt][0], a[mt][1], a[mt][2], a[mt][3],
                        a_b + (row * A_PITCH + col) * 2);
            }
#pragma unroll
            for (int np = 0; np < 4; np++) {
                int row = ks * 16 + (lane & 7) + ((lane >> 3) & 1) * 8;
                int col = warp_n * 64 + np * 16 + (lane >> 4) * 8;
                ldsm_x4t(b[np][0], b[np][1], b[np][2], b[np][3],
                         b_b + (row * B_PITCH + col) * 2);
            }
#pragma unroll
            for (int mt = 0; mt < 2; mt++)
#pragma unroll
                for (int nt = 0; nt < 8; nt++)
                    mma16816h(c[mt][nt], a[mt],
                              b[nt >> 1][(nt & 1) * 2], b[nt >> 1][(nt & 1) * 2 + 1]);
        }
        if (t + 1 < NT) {
            __syncthreads();
            STS_AB2(p ^ 1);
            __syncthreads();
        }
    }
#undef LDG_AB2
#undef STS_AB2

    const float* bias = warp_n ? blv : bmu;
    float* base = out + (warp_n ? (size_t)M * 64 : 0);
#pragma unroll
    for (int mt = 0; mt < 2; mt++) {
        int row0 = block_row + warp_m * 32 + mt * 16 + (lane >> 2);
        int row1 = row0 + 8;
#pragma unroll
        for (int nt = 0; nt < 8; nt++) {
            int col = nt * 8 + (lane & 3) * 2;
            float b0 = __ldg(&bias[col]), b1 = __ldg(&bias[col + 1]);
            if (row0 < M)
                *reinterpret_cast<float2*>(base + (size_t)row0 * 64 + col) =
                    make_float2(c[mt][nt][0] + b0, c[mt][nt][1] + b1);
            if (row1 < M)
                *reinterpret_cast<float2*>(base + (size_t)row1 * 64 + col) =
                    make_float2(c[mt][nt][2] + b0, c[mt][nt][3] + b1);
        }
    }
}

// ---------------- launch ---------------------------------------------------------------
extern "C" void kernel_launch(void* const* d_in, const int* in_sizes, int n_in,
                              void* d_out, int out_size) {
    const float* x   = (const float*)d_in[0];
    const int*   ei  = (const int*)d_in[1];   // int32 (JAX x64 disabled)
    const float* W1  = (const float*)d_in[2];
    const float* b1  = (const float*)d_in[3];
    const float* Wmu = (const float*)d_in[4];
    const float* bmu = (const float*)d_in[5];
    const float* Wlv = (const float*)d_in[6];
    const float* blv = (const float*)d_in[7];
    float* out = (float*)d_out;

    const int N = in_sizes[0] / F_IN;  // 50000
    const int E = in_sizes[1] / 2;     // 800000
    const int* src = ei;
    const int* dst = ei + E;

    __half *hs1, *hs2, *a2;
    cudaGetSymbolAddress((void**)&hs1, g_hs1h);
    cudaGetSymbolAddress((void**)&hs2, g_hs2h);
    cudaGetSymbolAddress((void**)&a2,  g_a2h);

    cudaFuncSetAttribute(mma_gemm1_kernel,
                         cudaFuncAttributeMaxDynamicSharedMemorySize, SM_BYTES);
    cudaFuncSetAttribute(mma_gemm2_kernel,
                         cudaFuncAttributeMaxDynamicSharedMemorySize, SM_BYTES);

    static cudaStream_t sB = nullptr;
    static cudaEvent_t evFork = nullptr, evJoin = nullptr;
    if (sB == nullptr) {
        cudaStreamCreateWithFlags(&sB, cudaStreamNonBlocking);
        cudaEventCreateWithFlags(&evFork, cudaEventDisableTiming);
        cudaEventCreateWithFlags(&evJoin, cudaEventDisableTiming);
    }

    // fork: stream B = GEMM1 only (weights converted in-kernel)
    cudaEventRecord(evFork, 0);
    cudaStreamWaitEvent(sB, evFork, 0);
    mma_gemm1_kernel<<<(N + 127) / 128, 256, SM_BYTES, sB>>>(x, W1, hs1, N);
    cudaEventRecord(evJoin, sB);

    // stream A (default): CSR build
    hist_kernel<<<(E / 4 + 255) / 256, 256>>>(dst, E);
    scan_kernel<<<NSCAN, SCAN_B>>>(N, E);
    place_kernel<<<(E / 2 + 255) / 256, 256>>>(src, dst, E);

    // join, then the dependent chain
    cudaStreamWaitEvent(0, evJoin, 0);
    agg1_kernel<<<(N * 32 + 255) / 256, 256>>>(hs1, b1, hs2, N);
    agg2_kernel<<<(N * 32 + 255) / 256, 256>>>(hs2, a2, N);
    mma_gemm2_kernel<<<(N + 127) / 128, 256, SM_BYTES>>>(a2, Wmu, Wlv, bmu, blv, out, N);
}